// round 6
// baseline (speedup 1.0000x reference)
#include <cuda_runtime.h>

// 2-layer LSTM (IN=16, H=32, T=512, B=4096) + MLP head, fully fused.
// R6: lane = hidden unit; warp = 8 sequences; 4 warps/block (1 per SMSP),
// 128 blocks. Weights in smem as gate j-pairs (LDS.128 -> aligned reg pairs,
// zero packing MOVs). Activations (h0/h1/x) staged in per-warp smem and read
// back via BROADCAST LDS.128 (1 wavefront, two j-pairs per load) -- replaces
// all mainloop shuffles. Layer1 computes Whh1*h1_prev before Wih1*h0_new so
// the cell nonlinearity latency hides under independent FFMA2 work.
// FMA-pipe floor: 1792 FFMA2/warp-step * 2cyc * 512 steps ~= 966us.

#define FULLMASK 0xffffffffu

constexpr int T_LEN = 512;
constexpr int IN_DIM = 16;
constexpr int H_DIM = 32;
constexpr int SEQ_PER_WARP = 8;
constexpr int WARPS_PER_BLOCK = 4;
constexpr int THREADS = WARPS_PER_BLOCK * 32;

// Weight arrays: [jp][unit] float4.
//  A = (wi[2jp], wi[2jp+1], wf[2jp], wf[2jp+1])
//  B = (wg[2jp], wg[2jp+1], wo[2jp], wo[2jp+1])
struct SmemW {
    float4 ihA0[IN_DIM / 2][H_DIM];
    float4 ihB0[IN_DIM / 2][H_DIM];
    float4 hhA0[H_DIM / 2][H_DIM];
    float4 hhB0[H_DIM / 2][H_DIM];
    float4 ihA1[H_DIM / 2][H_DIM];
    float4 ihB1[H_DIM / 2][H_DIM];
    float4 hhA1[H_DIM / 2][H_DIM];
    float4 hhB1[H_DIM / 2][H_DIM];
    float4 bg0[H_DIM];   // (bi, bf, bg, bo) per unit (bih+bhh)
    float4 bg1[H_DIM];
};

// Per-warp activation staging.
struct SmemStage {
    float h0[SEQ_PER_WARP][H_DIM];
    float h1[SEQ_PER_WARP][H_DIM];
    float x[SEQ_PER_WARP][IN_DIM];
};

struct SmemAll {
    SmemW w;
    SmemStage st[WARPS_PER_BLOCK];
};

typedef unsigned long long u64;

__device__ __forceinline__ u64 fma2(u64 a, u64 b, u64 c) {
    u64 d;
    asm("fma.rn.f32x2 %0, %1, %2, %3;" : "=l"(d) : "l"(a), "l"(b), "l"(c));
    return d;
}
__device__ __forceinline__ u64 pack2f(float a, float b) {
    u64 r;
    asm("mov.b64 %0, {%1, %2};" : "=l"(r) : "f"(a), "f"(b));
    return r;
}
__device__ __forceinline__ float2 unpack2(u64 v) {
    float2 r;
    asm("mov.b64 {%0, %1}, %2;" : "=f"(r.x), "=f"(r.y) : "l"(v));
    return r;
}
__device__ __forceinline__ float hsum2(u64 v) {
    float2 r = unpack2(v);
    return r.x + r.y;
}

__device__ __forceinline__ float fast_sigmoid(float x) {
    return __fdividef(1.0f, 1.0f + __expf(-x));
}
__device__ __forceinline__ float fast_tanh(float x) {
    float a = fabsf(x);
    float e = __expf(-2.0f * a);
    float r = __fdividef(1.0f - e, 1.0f + e);
    return copysignf(r, x);
}

__global__ void __launch_bounds__(THREADS, 1)
lstm_fused_kernel(const float* __restrict__ x,
                  const float* __restrict__ Wih0, const float* __restrict__ Whh0,
                  const float* __restrict__ bih0, const float* __restrict__ bhh0,
                  const float* __restrict__ Wih1, const float* __restrict__ Whh1,
                  const float* __restrict__ bih1, const float* __restrict__ bhh1,
                  const float* __restrict__ W1, const float* __restrict__ b1,
                  const float* __restrict__ W2, const float* __restrict__ b2,
                  float* __restrict__ out, int batch) {
    extern __shared__ char smem_raw[];
    SmemAll* sm = reinterpret_cast<SmemAll*>(smem_raw);
    SmemW* s = &sm->w;

    const int tid = threadIdx.x;

    // ---- Stage weights as gate j-pairs (block cooperative) ----
    for (int i = tid; i < (IN_DIM / 2) * H_DIM; i += THREADS) {
        int jp = i / H_DIM, u = i % H_DIM;
        int j0 = 2 * jp, j1 = 2 * jp + 1;
        s->ihA0[jp][u] = make_float4(Wih0[(0 * H_DIM + u) * IN_DIM + j0],
                                     Wih0[(0 * H_DIM + u) * IN_DIM + j1],
                                     Wih0[(1 * H_DIM + u) * IN_DIM + j0],
                                     Wih0[(1 * H_DIM + u) * IN_DIM + j1]);
        s->ihB0[jp][u] = make_float4(Wih0[(2 * H_DIM + u) * IN_DIM + j0],
                                     Wih0[(2 * H_DIM + u) * IN_DIM + j1],
                                     Wih0[(3 * H_DIM + u) * IN_DIM + j0],
                                     Wih0[(3 * H_DIM + u) * IN_DIM + j1]);
    }
    for (int i = tid; i < (H_DIM / 2) * H_DIM; i += THREADS) {
        int jp = i / H_DIM, u = i % H_DIM;
        int j0 = 2 * jp, j1 = 2 * jp + 1;
        s->hhA0[jp][u] = make_float4(Whh0[(0 * H_DIM + u) * H_DIM + j0],
                                     Whh0[(0 * H_DIM + u) * H_DIM + j1],
                                     Whh0[(1 * H_DIM + u) * H_DIM + j0],
                                     Whh0[(1 * H_DIM + u) * H_DIM + j1]);
        s->hhB0[jp][u] = make_float4(Whh0[(2 * H_DIM + u) * H_DIM + j0],
                                     Whh0[(2 * H_DIM + u) * H_DIM + j1],
                                     Whh0[(3 * H_DIM + u) * H_DIM + j0],
                                     Whh0[(3 * H_DIM + u) * H_DIM + j1]);
        s->ihA1[jp][u] = make_float4(Wih1[(0 * H_DIM + u) * H_DIM + j0],
                                     Wih1[(0 * H_DIM + u) * H_DIM + j1],
                                     Wih1[(1 * H_DIM + u) * H_DIM + j0],
                                     Wih1[(1 * H_DIM + u) * H_DIM + j1]);
        s->ihB1[jp][u] = make_float4(Wih1[(2 * H_DIM + u) * H_DIM + j0],
                                     Wih1[(2 * H_DIM + u) * H_DIM + j1],
                                     Wih1[(3 * H_DIM + u) * H_DIM + j0],
                                     Wih1[(3 * H_DIM + u) * H_DIM + j1]);
        s->hhA1[jp][u] = make_float4(Whh1[(0 * H_DIM + u) * H_DIM + j0],
                                     Whh1[(0 * H_DIM + u) * H_DIM + j1],
                                     Whh1[(1 * H_DIM + u) * H_DIM + j0],
                                     Whh1[(1 * H_DIM + u) * H_DIM + j1]);
        s->hhB1[jp][u] = make_float4(Whh1[(2 * H_DIM + u) * H_DIM + j0],
                                     Whh1[(2 * H_DIM + u) * H_DIM + j1],
                                     Whh1[(3 * H_DIM + u) * H_DIM + j0],
                                     Whh1[(3 * H_DIM + u) * H_DIM + j1]);
    }
    for (int u = tid; u < H_DIM; u += THREADS) {
        s->bg0[u] = make_float4(bih0[0 * H_DIM + u] + bhh0[0 * H_DIM + u],
                                bih0[1 * H_DIM + u] + bhh0[1 * H_DIM + u],
                                bih0[2 * H_DIM + u] + bhh0[2 * H_DIM + u],
                                bih0[3 * H_DIM + u] + bhh0[3 * H_DIM + u]);
        s->bg1[u] = make_float4(bih1[0 * H_DIM + u] + bhh1[0 * H_DIM + u],
                                bih1[1 * H_DIM + u] + bhh1[1 * H_DIM + u],
                                bih1[2 * H_DIM + u] + bhh1[2 * H_DIM + u],
                                bih1[3 * H_DIM + u] + bhh1[3 * H_DIM + u]);
    }
    __syncthreads();

    const int warp = tid >> 5;
    const int lane = tid & 31;    // lane = hidden unit
    SmemStage* st = &sm->st[warp];
    const int seq_base = (blockIdx.x * WARPS_PER_BLOCK + warp) * SEQ_PER_WARP;
    if (seq_base >= batch) return;  // batch % (8*4) == 0

    const float* xb = x + (size_t)seq_base * T_LEN * IN_DIM;
    const size_t seq_stride = (size_t)T_LEN * IN_DIM;

    // Gate biases packed (lo = bias, hi = 0).
    const float4 b0v = s->bg0[lane];
    const float4 b1v = s->bg1[lane];
    const u64 bi0 = pack2f(b0v.x, 0.f), bf0 = pack2f(b0v.y, 0.f);
    const u64 bg0_ = pack2f(b0v.z, 0.f), bo0 = pack2f(b0v.w, 0.f);
    const u64 bi1 = pack2f(b1v.x, 0.f), bf1 = pack2f(b1v.y, 0.f);
    const u64 bg1_ = pack2f(b1v.z, 0.f), bo1 = pack2f(b1v.w, 0.f);

    float c0f[SEQ_PER_WARP] = {0, 0, 0, 0, 0, 0, 0, 0};
    float c1f[SEQ_PER_WARP] = {0, 0, 0, 0, 0, 0, 0, 0};

    // Init staging: h0 = h1 = 0; x(t=0).
#pragma unroll
    for (int ss = 0; ss < SEQ_PER_WARP; ss++) {
        st->h0[ss][lane] = 0.f;
        st->h1[ss][lane] = 0.f;
    }
    {
        int ss = lane >> 2, q = lane & 3;  // lane -> (seq, quarter)
        float4 v = *reinterpret_cast<const float4*>(xb + ss * seq_stride + 4 * q);
        *reinterpret_cast<float4*>(&st->x[ss][4 * q]) = v;
    }
    __syncwarp();

    const int x_ss = lane >> 2, x_q = lane & 3;

    for (int t = 0; t < T_LEN; t++) {
        // Prefetch x(t+1) into registers (consumed by STS mid-iteration).
        float4 xn = make_float4(0.f, 0.f, 0.f, 0.f);
        if (t + 1 < T_LEN)
            xn = *reinterpret_cast<const float4*>(
                xb + x_ss * seq_stride + (t + 1) * IN_DIM + 4 * x_q);

        u64 ai[8], af[8], ag[8], ao[8];

        // ===== Layer 0: ih0 (x) -- bias folded into group 0 =====
#pragma unroll
        for (int g = 0; g < IN_DIM / 4; g++) {   // 4 groups of 2 jp
            ulonglong2 A0 = *reinterpret_cast<const ulonglong2*>(&s->ihA0[2 * g][lane]);
            ulonglong2 B0 = *reinterpret_cast<const ulonglong2*>(&s->ihB0[2 * g][lane]);
            ulonglong2 A1 = *reinterpret_cast<const ulonglong2*>(&s->ihA0[2 * g + 1][lane]);
            ulonglong2 B1 = *reinterpret_cast<const ulonglong2*>(&s->ihB0[2 * g + 1][lane]);
#pragma unroll
            for (int ss = 0; ss < 8; ss++) {
                ulonglong2 xv = *reinterpret_cast<const ulonglong2*>(&st->x[ss][4 * g]);
                if (g == 0) {
                    ai[ss] = fma2(A0.x, xv.x, bi0);
                    af[ss] = fma2(A0.y, xv.x, bf0);
                    ag[ss] = fma2(B0.x, xv.x, bg0_);
                    ao[ss] = fma2(B0.y, xv.x, bo0);
                } else {
                    ai[ss] = fma2(A0.x, xv.x, ai[ss]);
                    af[ss] = fma2(A0.y, xv.x, af[ss]);
                    ag[ss] = fma2(B0.x, xv.x, ag[ss]);
                    ao[ss] = fma2(B0.y, xv.x, ao[ss]);
                }
                ai[ss] = fma2(A1.x, xv.y, ai[ss]);
                af[ss] = fma2(A1.y, xv.y, af[ss]);
                ag[ss] = fma2(B1.x, xv.y, ag[ss]);
                ao[ss] = fma2(B1.y, xv.y, ao[ss]);
            }
        }
        // ===== Layer 0: hh0 (h0 prev) =====
#pragma unroll
        for (int g = 0; g < H_DIM / 4; g++) {    // 8 groups
            ulonglong2 A0 = *reinterpret_cast<const ulonglong2*>(&s->hhA0[2 * g][lane]);
            ulonglong2 B0 = *reinterpret_cast<const ulonglong2*>(&s->hhB0[2 * g][lane]);
            ulonglong2 A1 = *reinterpret_cast<const ulonglong2*>(&s->hhA0[2 * g + 1][lane]);
            ulonglong2 B1 = *reinterpret_cast<const ulonglong2*>(&s->hhB0[2 * g + 1][lane]);
#pragma unroll
            for (int ss = 0; ss < 8; ss++) {
                ulonglong2 hv = *reinterpret_cast<const ulonglong2*>(&st->h0[ss][4 * g]);
                ai[ss] = fma2(A0.x, hv.x, ai[ss]);
                af[ss] = fma2(A0.y, hv.x, af[ss]);
                ag[ss] = fma2(B0.x, hv.x, ag[ss]);
                ao[ss] = fma2(B0.y, hv.x, ao[ss]);
                ai[ss] = fma2(A1.x, hv.y, ai[ss]);
                af[ss] = fma2(A1.y, hv.y, af[ss]);
                ag[ss] = fma2(B1.x, hv.y, ag[ss]);
                ao[ss] = fma2(B1.y, hv.y, ao[ss]);
            }
        }
        // ===== Cell 0 + stage h0_new =====
#pragma unroll
        for (int ss = 0; ss < 8; ss++) {
            float ig = fast_sigmoid(hsum2(ai[ss]));
            float fg = fast_sigmoid(hsum2(af[ss]));
            float gg = fast_tanh(hsum2(ag[ss]));
            float og = fast_sigmoid(hsum2(ao[ss]));
            c0f[ss] = fmaf(fg, c0f[ss], ig * gg);
            st->h0[ss][lane] = og * fast_tanh(c0f[ss]);
        }
        __syncwarp();
        // Stage x(t+1) (layer0 reads of x(t) are done; sync above orders them).
        *reinterpret_cast<float4*>(&st->x[x_ss][4 * x_q]) = xn;

        // ===== Layer 1: hh1 first (h1 prev; independent of h0_new) =====
#pragma unroll
        for (int g = 0; g < H_DIM / 4; g++) {
            ulonglong2 A0 = *reinterpret_cast<const ulonglong2*>(&s->hhA1[2 * g][lane]);
            ulonglong2 B0 = *reinterpret_cast<const ulonglong2*>(&s->hhB1[2 * g][lane]);
            ulonglong2 A1 = *reinterpret_cast<const ulonglong2*>(&s->hhA1[2 * g + 1][lane]);
            ulonglong2 B1 = *reinterpret_cast<const ulonglong2*>(&s->hhB1[2 * g + 1][lane]);
#pragma unroll
            for (int ss = 0; ss < 8; ss++) {
                ulonglong2 hv = *reinterpret_cast<const ulonglong2*>(&st->h1[ss][4 * g]);
                if (g == 0) {
                    ai[ss] = fma2(A0.x, hv.x, bi1);
                    af[ss] = fma2(A0.y, hv.x, bf1);
                    ag[ss] = fma2(B0.x, hv.x, bg1_);
                    ao[ss] = fma2(B0.y, hv.x, bo1);
                } else {
                    ai[ss] = fma2(A0.x, hv.x, ai[ss]);
                    af[ss] = fma2(A0.y, hv.x, af[ss]);
                    ag[ss] = fma2(B0.x, hv.x, ag[ss]);
                    ao[ss] = fma2(B0.y, hv.x, ao[ss]);
                }
                ai[ss] = fma2(A1.x, hv.y, ai[ss]);
                af[ss] = fma2(A1.y, hv.y, af[ss]);
                ag[ss] = fma2(B1.x, hv.y, ag[ss]);
                ao[ss] = fma2(B1.y, hv.y, ao[ss]);
            }
        }
        // ===== Layer 1: ih1 (h0_new, staged above) =====
#pragma unroll
        for (int g = 0; g < H_DIM / 4; g++) {
            ulonglong2 A0 = *reinterpret_cast<const ulonglong2*>(&s->ihA1[2 * g][lane]);
            ulonglong2 B0 = *reinterpret_cast<const ulonglong2*>(&s->ihB1[2 * g][lane]);
            ulonglong2 A1 = *reinterpret_cast<const ulonglong2*>(&s->ihA1[2 * g + 1][lane]);
            ulonglong2 B1 = *reinterpret_cast<const ulonglong2*>(&s->ihB1[2 * g + 1][lane]);
#pragma unroll
            for (int ss = 0; ss < 8; ss++) {
                ulonglong2 hv = *reinterpret_cast<const ulonglong2*>(&st->h0[ss][4 * g]);
                ai[ss] = fma2(A0.x, hv.x, ai[ss]);
                af[ss] = fma2(A0.y, hv.x, af[ss]);
                ag[ss] = fma2(B0.x, hv.x, ag[ss]);
                ao[ss] = fma2(B0.y, hv.x, ao[ss]);
                ai[ss] = fma2(A1.x, hv.y, ai[ss]);
                af[ss] = fma2(A1.y, hv.y, af[ss]);
                ag[ss] = fma2(B1.x, hv.y, ag[ss]);
                ao[ss] = fma2(B1.y, hv.y, ao[ss]);
            }
        }
        // ===== Cell 1 + stage h1_new =====
#pragma unroll
        for (int ss = 0; ss < 8; ss++) {
            float ig = fast_sigmoid(hsum2(ai[ss]));
            float fg = fast_sigmoid(hsum2(af[ss]));
            float gg = fast_tanh(hsum2(ag[ss]));
            float og = fast_sigmoid(hsum2(ao[ss]));
            c1f[ss] = fmaf(fg, c1f[ss], ig * gg);
            st->h1[ss][lane] = og * fast_tanh(c1f[ss]);
        }
        __syncwarp();  // h1/x stores visible before next iteration's reads
    }

    // ---- Head: z = relu(h1 @ W1.T + b1); y = z @ W2.T + b2 ----
    // Lane m (<16) computes z[m] per sequence, reading h1 from smem broadcast.
    float bias2 = __ldg(b2);
    float bm = (lane < 16) ? __ldg(b1 + lane) : 0.f;
    float w2m = (lane < 16) ? __ldg(W2 + lane) : 0.f;
#pragma unroll
    for (int ss = 0; ss < SEQ_PER_WARP; ss++) {
        float z = bm;
#pragma unroll
        for (int j = 0; j < H_DIM; j++) {
            float wm = (lane < 16) ? __ldg(W1 + lane * H_DIM + j) : 0.f;
            z = fmaf(wm, st->h1[ss][j], z);
        }
        float v = fmaxf(z, 0.f) * w2m;
#pragma unroll
        for (int off = 8; off >= 1; off >>= 1)
            v += __shfl_xor_sync(FULLMASK, v, off, 16);
        if (lane == 0) out[seq_base + ss] = v + bias2;
    }
}

extern "C" void kernel_launch(void* const* d_in, const int* in_sizes, int n_in,
                              void* d_out, int out_size) {
    const float* x    = (const float*)d_in[0];
    const float* Wih0 = (const float*)d_in[1];
    const float* Whh0 = (const float*)d_in[2];
    const float* bih0 = (const float*)d_in[3];
    const float* bhh0 = (const float*)d_in[4];
    const float* Wih1 = (const float*)d_in[5];
    const float* Whh1 = (const float*)d_in[6];
    const float* bih1 = (const float*)d_in[7];
    const float* bhh1 = (const float*)d_in[8];
    const float* W1   = (const float*)d_in[9];
    const float* b1   = (const float*)d_in[10];
    const float* W2   = (const float*)d_in[11];
    const float* b2   = (const float*)d_in[12];
    float* out = (float*)d_out;

    int batch = in_sizes[0] / (T_LEN * IN_DIM);  // 4096

    cudaFuncSetAttribute(lstm_fused_kernel,
                         cudaFuncAttributeMaxDynamicSharedMemorySize,
                         (int)sizeof(SmemAll));

    int warps_needed = (batch + SEQ_PER_WARP - 1) / SEQ_PER_WARP;        // 512
    int blocks = (warps_needed + WARPS_PER_BLOCK - 1) / WARPS_PER_BLOCK; // 128
    lstm_fused_kernel<<<blocks, THREADS, sizeof(SmemAll)>>>(
        x, Wih0, Whh0, bih0, bhh0, Wih1, Whh1, bih1, bhh1,
        W1, b1, W2, b2, out, batch);
}

// round 7
// speedup vs baseline: 1.5215x; 1.5215x over previous
#include <cuda_runtime.h>

// 2-layer LSTM (IN=16, H=32, T=512, B=4096) + MLP head, fully fused.
// R7 = R5 latency-hiding point (S=4 seqs/warp, 7 warps/block, 1024 warps,
// ~7 warps/SM) + R6 smem-staged activations (broadcast LDS.128 replaces all
// mainloop shuffles; ~470 SHFL/warp-step removed from the LSU pipe).
// Weights in smem as gate j-pairs -> LDS.128 lands aligned register pairs,
// FFMA2 (fma.rn.f32x2) with zero packing MOVs. Accumulators: 16 u64.
// Layer1 computes Whh1*h1_prev before Wih1*h0_new to hide cell latency.

#define FULLMASK 0xffffffffu

constexpr int T_LEN = 512;
constexpr int IN_DIM = 16;
constexpr int H_DIM = 32;
constexpr int SEQ_PER_WARP = 4;
constexpr int WARPS_PER_BLOCK = 7;
constexpr int THREADS = WARPS_PER_BLOCK * 32;

// Weight arrays: [jp][unit] float4.
//  A = (wi[2jp], wi[2jp+1], wf[2jp], wf[2jp+1])
//  B = (wg[2jp], wg[2jp+1], wo[2jp], wo[2jp+1])
struct SmemW {
    float4 ihA0[IN_DIM / 2][H_DIM];
    float4 ihB0[IN_DIM / 2][H_DIM];
    float4 hhA0[H_DIM / 2][H_DIM];
    float4 hhB0[H_DIM / 2][H_DIM];
    float4 ihA1[H_DIM / 2][H_DIM];
    float4 ihB1[H_DIM / 2][H_DIM];
    float4 hhA1[H_DIM / 2][H_DIM];
    float4 hhB1[H_DIM / 2][H_DIM];
    float4 bg0[H_DIM];   // (bi, bf, bg, bo) per unit (bih+bhh)
    float4 bg1[H_DIM];
};

// Per-warp activation staging (read via broadcast LDS.128).
struct SmemStage {
    float h0[SEQ_PER_WARP][H_DIM];
    float h1[SEQ_PER_WARP][H_DIM];
    float x[SEQ_PER_WARP][IN_DIM];
};

struct SmemAll {
    SmemW w;
    SmemStage st[WARPS_PER_BLOCK];
};

typedef unsigned long long u64;

__device__ __forceinline__ u64 fma2(u64 a, u64 b, u64 c) {
    u64 d;
    asm("fma.rn.f32x2 %0, %1, %2, %3;" : "=l"(d) : "l"(a), "l"(b), "l"(c));
    return d;
}
__device__ __forceinline__ u64 pack2f(float a, float b) {
    u64 r;
    asm("mov.b64 %0, {%1, %2};" : "=l"(r) : "f"(a), "f"(b));
    return r;
}
__device__ __forceinline__ float2 unpack2(u64 v) {
    float2 r;
    asm("mov.b64 {%0, %1}, %2;" : "=f"(r.x), "=f"(r.y) : "l"(v));
    return r;
}
__device__ __forceinline__ float hsum2(u64 v) {
    float2 r = unpack2(v);
    return r.x + r.y;
}

__device__ __forceinline__ float fast_sigmoid(float x) {
    return __fdividef(1.0f, 1.0f + __expf(-x));
}
__device__ __forceinline__ float fast_tanh(float x) {
    float a = fabsf(x);
    float e = __expf(-2.0f * a);
    float r = __fdividef(1.0f - e, 1.0f + e);
    return copysignf(r, x);
}

__global__ void __launch_bounds__(THREADS, 1)
lstm_fused_kernel(const float* __restrict__ x,
                  const float* __restrict__ Wih0, const float* __restrict__ Whh0,
                  const float* __restrict__ bih0, const float* __restrict__ bhh0,
                  const float* __restrict__ Wih1, const float* __restrict__ Whh1,
                  const float* __restrict__ bih1, const float* __restrict__ bhh1,
                  const float* __restrict__ W1, const float* __restrict__ b1,
                  const float* __restrict__ W2, const float* __restrict__ b2,
                  float* __restrict__ out, int batch) {
    extern __shared__ char smem_raw[];
    SmemAll* sm = reinterpret_cast<SmemAll*>(smem_raw);
    SmemW* s = &sm->w;

    const int tid = threadIdx.x;

    // ---- Stage weights as gate j-pairs (block cooperative) ----
    for (int i = tid; i < (IN_DIM / 2) * H_DIM; i += THREADS) {
        int jp = i / H_DIM, u = i % H_DIM;
        int j0 = 2 * jp, j1 = 2 * jp + 1;
        s->ihA0[jp][u] = make_float4(Wih0[(0 * H_DIM + u) * IN_DIM + j0],
                                     Wih0[(0 * H_DIM + u) * IN_DIM + j1],
                                     Wih0[(1 * H_DIM + u) * IN_DIM + j0],
                                     Wih0[(1 * H_DIM + u) * IN_DIM + j1]);
        s->ihB0[jp][u] = make_float4(Wih0[(2 * H_DIM + u) * IN_DIM + j0],
                                     Wih0[(2 * H_DIM + u) * IN_DIM + j1],
                                     Wih0[(3 * H_DIM + u) * IN_DIM + j0],
                                     Wih0[(3 * H_DIM + u) * IN_DIM + j1]);
    }
    for (int i = tid; i < (H_DIM / 2) * H_DIM; i += THREADS) {
        int jp = i / H_DIM, u = i % H_DIM;
        int j0 = 2 * jp, j1 = 2 * jp + 1;
        s->hhA0[jp][u] = make_float4(Whh0[(0 * H_DIM + u) * H_DIM + j0],
                                     Whh0[(0 * H_DIM + u) * H_DIM + j1],
                                     Whh0[(1 * H_DIM + u) * H_DIM + j0],
                                     Whh0[(1 * H_DIM + u) * H_DIM + j1]);
        s->hhB0[jp][u] = make_float4(Whh0[(2 * H_DIM + u) * H_DIM + j0],
                                     Whh0[(2 * H_DIM + u) * H_DIM + j1],
                                     Whh0[(3 * H_DIM + u) * H_DIM + j0],
                                     Whh0[(3 * H_DIM + u) * H_DIM + j1]);
        s->ihA1[jp][u] = make_float4(Wih1[(0 * H_DIM + u) * H_DIM + j0],
                                     Wih1[(0 * H_DIM + u) * H_DIM + j1],
                                     Wih1[(1 * H_DIM + u) * H_DIM + j0],
                                     Wih1[(1 * H_DIM + u) * H_DIM + j1]);
        s->ihB1[jp][u] = make_float4(Wih1[(2 * H_DIM + u) * H_DIM + j0],
                                     Wih1[(2 * H_DIM + u) * H_DIM + j1],
                                     Wih1[(3 * H_DIM + u) * H_DIM + j0],
                                     Wih1[(3 * H_DIM + u) * H_DIM + j1]);
        s->hhA1[jp][u] = make_float4(Whh1[(0 * H_DIM + u) * H_DIM + j0],
                                     Whh1[(0 * H_DIM + u) * H_DIM + j1],
                                     Whh1[(1 * H_DIM + u) * H_DIM + j0],
                                     Whh1[(1 * H_DIM + u) * H_DIM + j1]);
        s->hhB1[jp][u] = make_float4(Whh1[(2 * H_DIM + u) * H_DIM + j0],
                                     Whh1[(2 * H_DIM + u) * H_DIM + j1],
                                     Whh1[(3 * H_DIM + u) * H_DIM + j0],
                                     Whh1[(3 * H_DIM + u) * H_DIM + j1]);
    }
    for (int u = tid; u < H_DIM; u += THREADS) {
        s->bg0[u] = make_float4(bih0[0 * H_DIM + u] + bhh0[0 * H_DIM + u],
                                bih0[1 * H_DIM + u] + bhh0[1 * H_DIM + u],
                                bih0[2 * H_DIM + u] + bhh0[2 * H_DIM + u],
                                bih0[3 * H_DIM + u] + bhh0[3 * H_DIM + u]);
        s->bg1[u] = make_float4(bih1[0 * H_DIM + u] + bhh1[0 * H_DIM + u],
                                bih1[1 * H_DIM + u] + bhh1[1 * H_DIM + u],
                                bih1[2 * H_DIM + u] + bhh1[2 * H_DIM + u],
                                bih1[3 * H_DIM + u] + bhh1[3 * H_DIM + u]);
    }
    __syncthreads();

    const int warp = tid >> 5;
    const int lane = tid & 31;    // lane = hidden unit
    SmemStage* st = &sm->st[warp];
    const int seq_base = (blockIdx.x * WARPS_PER_BLOCK + warp) * SEQ_PER_WARP;
    if (seq_base >= batch) return;  // batch 4096 = 1024 warps; grid has 1029

    const float* xb = x + (size_t)seq_base * T_LEN * IN_DIM;
    const size_t seq_stride = (size_t)T_LEN * IN_DIM;

    // Gate biases packed (lo = bias, hi = 0).
    const float4 b0v = s->bg0[lane];
    const float4 b1v = s->bg1[lane];
    const u64 bi0 = pack2f(b0v.x, 0.f), bf0 = pack2f(b0v.y, 0.f);
    const u64 bg0_ = pack2f(b0v.z, 0.f), bo0 = pack2f(b0v.w, 0.f);
    const u64 bi1 = pack2f(b1v.x, 0.f), bf1 = pack2f(b1v.y, 0.f);
    const u64 bg1_ = pack2f(b1v.z, 0.f), bo1 = pack2f(b1v.w, 0.f);

    float c0f[SEQ_PER_WARP] = {0, 0, 0, 0};
    float c1f[SEQ_PER_WARP] = {0, 0, 0, 0};

    // Init staging: h0 = h1 = 0; x(t=0).
#pragma unroll
    for (int ss = 0; ss < SEQ_PER_WARP; ss++) {
        st->h0[ss][lane] = 0.f;
        st->h1[ss][lane] = 0.f;
    }
    const int x_ss = lane >> 2, x_q = lane & 3;  // lanes 0..15 carry x
    if (lane < 16) {
        float4 v = *reinterpret_cast<const float4*>(xb + x_ss * seq_stride + 4 * x_q);
        *reinterpret_cast<float4*>(&st->x[x_ss][4 * x_q]) = v;
    }
    __syncwarp();

    for (int t = 0; t < T_LEN; t++) {
        // Prefetch x(t+1) into registers (stored to smem mid-iteration).
        float4 xn = make_float4(0.f, 0.f, 0.f, 0.f);
        if (t + 1 < T_LEN && lane < 16)
            xn = *reinterpret_cast<const float4*>(
                xb + x_ss * seq_stride + (t + 1) * IN_DIM + 4 * x_q);

        u64 ai[4], af[4], ag[4], ao[4];

        // ===== Layer 0: ih0 (x), bias folded into group 0 =====
#pragma unroll
        for (int g = 0; g < IN_DIM / 4; g++) {   // 4 groups of 2 jp
            ulonglong2 A0 = *reinterpret_cast<const ulonglong2*>(&s->ihA0[2 * g][lane]);
            ulonglong2 B0 = *reinterpret_cast<const ulonglong2*>(&s->ihB0[2 * g][lane]);
            ulonglong2 A1 = *reinterpret_cast<const ulonglong2*>(&s->ihA0[2 * g + 1][lane]);
            ulonglong2 B1 = *reinterpret_cast<const ulonglong2*>(&s->ihB0[2 * g + 1][lane]);
#pragma unroll
            for (int ss = 0; ss < 4; ss++) {
                ulonglong2 xv = *reinterpret_cast<const ulonglong2*>(&st->x[ss][4 * g]);
                if (g == 0) {
                    ai[ss] = fma2(A0.x, xv.x, bi0);
                    af[ss] = fma2(A0.y, xv.x, bf0);
                    ag[ss] = fma2(B0.x, xv.x, bg0_);
                    ao[ss] = fma2(B0.y, xv.x, bo0);
                } else {
                    ai[ss] = fma2(A0.x, xv.x, ai[ss]);
                    af[ss] = fma2(A0.y, xv.x, af[ss]);
                    ag[ss] = fma2(B0.x, xv.x, ag[ss]);
                    ao[ss] = fma2(B0.y, xv.x, ao[ss]);
                }
                ai[ss] = fma2(A1.x, xv.y, ai[ss]);
                af[ss] = fma2(A1.y, xv.y, af[ss]);
                ag[ss] = fma2(B1.x, xv.y, ag[ss]);
                ao[ss] = fma2(B1.y, xv.y, ao[ss]);
            }
        }
        // ===== Layer 0: hh0 (h0 prev) =====
#pragma unroll
        for (int g = 0; g < H_DIM / 4; g++) {    // 8 groups
            ulonglong2 A0 = *reinterpret_cast<const ulonglong2*>(&s->hhA0[2 * g][lane]);
            ulonglong2 B0 = *reinterpret_cast<const ulonglong2*>(&s->hhB0[2 * g][lane]);
            ulonglong2 A1 = *reinterpret_cast<const ulonglong2*>(&s->hhA0[2 * g + 1][lane]);
            ulonglong2 B1 = *reinterpret_cast<const ulonglong2*>(&s->hhB0[2 * g + 1][lane]);
#pragma unroll
            for (int ss = 0; ss < 4; ss++) {
                ulonglong2 hv = *reinterpret_cast<const ulonglong2*>(&st->h0[ss][4 * g]);
                ai[ss] = fma2(A0.x, hv.x, ai[ss]);
                af[ss] = fma2(A0.y, hv.x, af[ss]);
                ag[ss] = fma2(B0.x, hv.x, ag[ss]);
                ao[ss] = fma2(B0.y, hv.x, ao[ss]);
                ai[ss] = fma2(A1.x, hv.y, ai[ss]);
                af[ss] = fma2(A1.y, hv.y, af[ss]);
                ag[ss] = fma2(B1.x, hv.y, ag[ss]);
                ao[ss] = fma2(B1.y, hv.y, ao[ss]);
            }
        }
        // ===== Cell 0 + stage h0_new =====
#pragma unroll
        for (int ss = 0; ss < 4; ss++) {
            float ig = fast_sigmoid(hsum2(ai[ss]));
            float fg = fast_sigmoid(hsum2(af[ss]));
            float gg = fast_tanh(hsum2(ag[ss]));
            float og = fast_sigmoid(hsum2(ao[ss]));
            c0f[ss] = fmaf(fg, c0f[ss], ig * gg);
            st->h0[ss][lane] = og * fast_tanh(c0f[ss]);
        }
        __syncwarp();
        // Stage x(t+1) (layer0 reads of x(t) done; ordered by the sync above).
        if (lane < 16)
            *reinterpret_cast<float4*>(&st->x[x_ss][4 * x_q]) = xn;

        // ===== Layer 1: hh1 first (h1 prev; independent of h0_new) =====
#pragma unroll
        for (int g = 0; g < H_DIM / 4; g++) {
            ulonglong2 A0 = *reinterpret_cast<const ulonglong2*>(&s->hhA1[2 * g][lane]);
            ulonglong2 B0 = *reinterpret_cast<const ulonglong2*>(&s->hhB1[2 * g][lane]);
            ulonglong2 A1 = *reinterpret_cast<const ulonglong2*>(&s->hhA1[2 * g + 1][lane]);
            ulonglong2 B1 = *reinterpret_cast<const ulonglong2*>(&s->hhB1[2 * g + 1][lane]);
#pragma unroll
            for (int ss = 0; ss < 4; ss++) {
                ulonglong2 hv = *reinterpret_cast<const ulonglong2*>(&st->h1[ss][4 * g]);
                if (g == 0) {
                    ai[ss] = fma2(A0.x, hv.x, bi1);
                    af[ss] = fma2(A0.y, hv.x, bf1);
                    ag[ss] = fma2(B0.x, hv.x, bg1_);
                    ao[ss] = fma2(B0.y, hv.x, bo1);
                } else {
                    ai[ss] = fma2(A0.x, hv.x, ai[ss]);
                    af[ss] = fma2(A0.y, hv.x, af[ss]);
                    ag[ss] = fma2(B0.x, hv.x, ag[ss]);
                    ao[ss] = fma2(B0.y, hv.x, ao[ss]);
                }
                ai[ss] = fma2(A1.x, hv.y, ai[ss]);
                af[ss] = fma2(A1.y, hv.y, af[ss]);
                ag[ss] = fma2(B1.x, hv.y, ag[ss]);
                ao[ss] = fma2(B1.y, hv.y, ao[ss]);
            }
        }
        // ===== Layer 1: ih1 (h0_new, staged above) =====
#pragma unroll
        for (int g = 0; g < H_DIM / 4; g++) {
            ulonglong2 A0 = *reinterpret_cast<const ulonglong2*>(&s->ihA1[2 * g][lane]);
            ulonglong2 B0 = *reinterpret_cast<const ulonglong2*>(&s->ihB1[2 * g][lane]);
            ulonglong2 A1 = *reinterpret_cast<const ulonglong2*>(&s->ihA1[2 * g + 1][lane]);
            ulonglong2 B1 = *reinterpret_cast<const ulonglong2*>(&s->ihB1[2 * g + 1][lane]);
#pragma unroll
            for (int ss = 0; ss < 4; ss++) {
                ulonglong2 hv = *reinterpret_cast<const ulonglong2*>(&st->h0[ss][4 * g]);
                ai[ss] = fma2(A0.x, hv.x, ai[ss]);
                af[ss] = fma2(A0.y, hv.x, af[ss]);
                ag[ss] = fma2(B0.x, hv.x, ag[ss]);
                ao[ss] = fma2(B0.y, hv.x, ao[ss]);
                ai[ss] = fma2(A1.x, hv.y, ai[ss]);
                af[ss] = fma2(A1.y, hv.y, af[ss]);
                ag[ss] = fma2(B1.x, hv.y, ag[ss]);
                ao[ss] = fma2(B1.y, hv.y, ao[ss]);
            }
        }
        // ===== Cell 1 + stage h1_new =====
#pragma unroll
        for (int ss = 0; ss < 4; ss++) {
            float ig = fast_sigmoid(hsum2(ai[ss]));
            float fg = fast_sigmoid(hsum2(af[ss]));
            float gg = fast_tanh(hsum2(ag[ss]));
            float og = fast_sigmoid(hsum2(ao[ss]));
            c1f[ss] = fmaf(fg, c1f[ss], ig * gg);
            st->h1[ss][lane] = og * fast_tanh(c1f[ss]);
        }
        __syncwarp();  // h1/x stores visible before next iteration's reads
    }

    // ---- Head: z = relu(h1 @ W1.T + b1); y = z @ W2.T + b2 ----
    float bias2 = __ldg(b2);
    float bm = (lane < 16) ? __ldg(b1 + lane) : 0.f;
    float w2m = (lane < 16) ? __ldg(W2 + lane) : 0.f;
#pragma unroll
    for (int ss = 0; ss < SEQ_PER_WARP; ss++) {
        float z = bm;
#pragma unroll
        for (int j = 0; j < H_DIM; j++) {
            float wm = (lane < 16) ? __ldg(W1 + lane * H_DIM + j) : 0.f;
            z = fmaf(wm, st->h1[ss][j], z);
        }
        float v = fmaxf(z, 0.f) * w2m;
#pragma unroll
        for (int off = 8; off >= 1; off >>= 1)
            v += __shfl_xor_sync(FULLMASK, v, off, 16);
        if (lane == 0) out[seq_base + ss] = v + bias2;
    }
}

extern "C" void kernel_launch(void* const* d_in, const int* in_sizes, int n_in,
                              void* d_out, int out_size) {
    const float* x    = (const float*)d_in[0];
    const float* Wih0 = (const float*)d_in[1];
    const float* Whh0 = (const float*)d_in[2];
    const float* bih0 = (const float*)d_in[3];
    const float* bhh0 = (const float*)d_in[4];
    const float* Wih1 = (const float*)d_in[5];
    const float* Whh1 = (const float*)d_in[6];
    const float* bih1 = (const float*)d_in[7];
    const float* bhh1 = (const float*)d_in[8];
    const float* W1   = (const float*)d_in[9];
    const float* b1   = (const float*)d_in[10];
    const float* W2   = (const float*)d_in[11];
    const float* b2   = (const float*)d_in[12];
    float* out = (float*)d_out;

    int batch = in_sizes[0] / (T_LEN * IN_DIM);  // 4096

    cudaFuncSetAttribute(lstm_fused_kernel,
                         cudaFuncAttributeMaxDynamicSharedMemorySize,
                         (int)sizeof(SmemAll));

    int warps_needed = (batch + SEQ_PER_WARP - 1) / SEQ_PER_WARP;        // 1024
    int blocks = (warps_needed + WARPS_PER_BLOCK - 1) / WARPS_PER_BLOCK; // 147
    lstm_fused_kernel<<<blocks, THREADS, sizeof(SmemAll)>>>(
        x, Wih0, Whh0, bih0, bhh0, Wih1, Whh1, bih1, bhh1,
        W1, b1, W2, b2, out, batch);
}